// round 1
// baseline (speedup 1.0000x reference)
#include <cuda_runtime.h>
#include <math.h>

// Problem constants (fixed by the dataset)
#define NN 50000
#define EE 1600000
// layer dims: IN=128, HID=32, OUT=32, HEADS=(4,4,6)

// ---------------------------------------------------------------------------
// Scratch (device globals; no allocation allowed)
// ---------------------------------------------------------------------------
__device__ float g_h1[NN * 128];     // layer1 output
__device__ float g_h2[NN * 128];     // layer2 output
__device__ float g_feat[NN * 192];   // per-layer feat = h @ W
__device__ float g_res[NN * 192];    // layer3 linear residual h2 @ resW3
__device__ float g_rst3[NN * 192];   // layer3 pre-mean output
__device__ float g_el[NN * 6];
__device__ float g_er[NN * 6];
__device__ float g_ebuf[EE * 6];     // per-edge attention scratch (CSR order)
__device__ int   g_rowptr[NN + 1];
__device__ int   g_cursor[NN];
__device__ int   g_csrsrc[EE];

// ---------------------------------------------------------------------------
// CSR build: histogram -> scan -> scatter (by dst)
// ---------------------------------------------------------------------------
__global__ void zero_cursor_k() {
    int i = blockIdx.x * blockDim.x + threadIdx.x;
    if (i < NN) g_cursor[i] = 0;
}

__global__ void count_k(const int* __restrict__ dst) {
    int e = blockIdx.x * blockDim.x + threadIdx.x;
    if (e < EE) atomicAdd(&g_cursor[dst[e]], 1);
}

// single-block exclusive scan over N counts; writes g_rowptr and resets g_cursor
__global__ void scan_k() {
    const int NT = 1024;
    const int SEG = (NN + NT - 1) / NT;
    __shared__ int s[NT];
    int t = threadIdx.x;
    int lo = t * SEG;
    int hi = lo + SEG; if (hi > NN) hi = NN;
    int sum = 0;
    for (int i = lo; i < hi; i++) sum += g_cursor[i];
    s[t] = sum;
    __syncthreads();
    for (int d = 1; d < NT; d <<= 1) {
        int v = (t >= d) ? s[t - d] : 0;
        __syncthreads();
        s[t] += v;
        __syncthreads();
    }
    int run = (t == 0) ? 0 : s[t - 1];
    for (int i = lo; i < hi; i++) {
        int c = g_cursor[i];
        g_rowptr[i] = run;
        g_cursor[i] = run;
        run += c;
    }
    if (t == NT - 1) g_rowptr[NN] = run;
}

__global__ void scatter_k(const int* __restrict__ src, const int* __restrict__ dst) {
    int e = blockIdx.x * blockDim.x + threadIdx.x;
    if (e < EE) {
        int d = dst[e];
        int p = atomicAdd(&g_cursor[d], 1);
        g_csrsrc[p] = src[e];
    }
}

// ---------------------------------------------------------------------------
// GEMM: C[N,M] = A[N,128] @ W[128,M]   (warp per node, A row in regs via shfl)
// ---------------------------------------------------------------------------
template <int M>
__global__ void gemm_k(const float* __restrict__ A,
                       const float* __restrict__ W,
                       float* __restrict__ C) {
    int n = (blockIdx.x * blockDim.x + threadIdx.x) >> 5;
    if (n >= NN) return;
    int lane = threadIdx.x & 31;

    const float4* A4 = reinterpret_cast<const float4*>(A) + (size_t)n * 32 + lane;
    float4 a = *A4;   // elements 4*lane .. 4*lane+3 of row n

    constexpr int MC = M / 4;            // float4 chunks per row (32 or 48)
    constexpr int NI = (MC + 31) / 32;   // chunks per lane (1 or 2)
    float4 acc[NI];
#pragma unroll
    for (int i = 0; i < NI; i++) acc[i] = make_float4(0.f, 0.f, 0.f, 0.f);

    const float4* W4 = reinterpret_cast<const float4*>(W);

#pragma unroll 16
    for (int k = 0; k < 128; k++) {
        float comp = ((k & 3) == 0) ? a.x : ((k & 3) == 1) ? a.y : ((k & 3) == 2) ? a.z : a.w;
        float ak = __shfl_sync(0xffffffffu, comp, k >> 2);
#pragma unroll
        for (int i = 0; i < NI; i++) {
            int c = lane + 32 * i;
            if ((MC % 32 == 0) || (c < MC)) {
                float4 w = W4[(size_t)k * MC + c];
                acc[i].x += ak * w.x;
                acc[i].y += ak * w.y;
                acc[i].z += ak * w.z;
                acc[i].w += ak * w.w;
            }
        }
    }

    float4* C4 = reinterpret_cast<float4*>(C);
#pragma unroll
    for (int i = 0; i < NI; i++) {
        int c = lane + 32 * i;
        if ((MC % 32 == 0) || (c < MC)) C4[(size_t)n * MC + c] = acc[i];
    }
}

// ---------------------------------------------------------------------------
// Attention projections: el[n,h] = <feat[n,h,:], al[h,:]>, er likewise
// ---------------------------------------------------------------------------
template <int H>
__global__ void attn_k(const float* __restrict__ feat,
                       const float* __restrict__ al,
                       const float* __restrict__ ar) {
    int i = blockIdx.x * blockDim.x + threadIdx.x;
    if (i >= NN * H) return;
    int n = i / H, h = i - n * H;
    const float4* f  = reinterpret_cast<const float4*>(feat) + (size_t)n * (H * 8) + h * 8;
    const float4* a4 = reinterpret_cast<const float4*>(al) + h * 8;
    const float4* r4 = reinterpret_cast<const float4*>(ar) + h * 8;
    float el = 0.f, er = 0.f;
#pragma unroll
    for (int j = 0; j < 8; j++) {
        float4 fv = f[j], av = a4[j], rv = r4[j];
        el += fv.x * av.x + fv.y * av.y + fv.z * av.z + fv.w * av.w;
        er += fv.x * rv.x + fv.y * rv.y + fv.z * rv.z + fv.w * rv.w;
    }
    g_el[i] = el;
    g_er[i] = er;
}

// ---------------------------------------------------------------------------
// Fused GAT aggregation: warp per dst node, atomic-free softmax + scatter
//   RES: add `res` array (identity or linear residual); ACT: elu
// ---------------------------------------------------------------------------
template <int H, bool RES, bool ACT>
__global__ void gat_k(const float* __restrict__ feat,
                      const float* __restrict__ res,
                      const float* __restrict__ bias,
                      float* __restrict__ out) {
    constexpr int C  = H * 8;            // float4 chunks per node (32 or 48)
    constexpr int NI = (C + 31) / 32;
    int n = (blockIdx.x * blockDim.x + threadIdx.x) >> 5;
    if (n >= NN) return;
    int lane = threadIdx.x & 31;

    int s0 = g_rowptr[n], s1 = g_rowptr[n + 1];

    float ern[H];
#pragma unroll
    for (int h = 0; h < H; h++) ern[h] = g_er[n * H + h];

    // phase 1: e = leakyrelu(el[src] + er[n]); track max
    float mx[H];
#pragma unroll
    for (int h = 0; h < H; h++) mx[h] = -1e30f;
    for (int p = s0 + lane; p < s1; p += 32) {
        int s = g_csrsrc[p];
#pragma unroll
        for (int h = 0; h < H; h++) {
            float e = g_el[s * H + h] + ern[h];
            e = (e > 0.f) ? e : 0.2f * e;
            g_ebuf[(size_t)p * H + h] = e;
            mx[h] = fmaxf(mx[h], e);
        }
    }
#pragma unroll
    for (int h = 0; h < H; h++) {
#pragma unroll
        for (int o = 16; o > 0; o >>= 1)
            mx[h] = fmaxf(mx[h], __shfl_xor_sync(0xffffffffu, mx[h], o));
    }

    // phase 2: ex = exp(e - m); sum
    float sm[H];
#pragma unroll
    for (int h = 0; h < H; h++) sm[h] = 0.f;
    for (int p = s0 + lane; p < s1; p += 32) {
#pragma unroll
        for (int h = 0; h < H; h++) {
            float ex = __expf(g_ebuf[(size_t)p * H + h] - mx[h]);
            g_ebuf[(size_t)p * H + h] = ex;
            sm[h] += ex;
        }
    }
#pragma unroll
    for (int h = 0; h < H; h++) {
#pragma unroll
        for (int o = 16; o > 0; o >>= 1)
            sm[h] += __shfl_xor_sync(0xffffffffu, sm[h], o);
    }
    float inv[H];
#pragma unroll
    for (int h = 0; h < H; h++) inv[h] = (sm[h] > 0.f) ? (1.f / sm[h]) : 0.f;

    // phase 2.5: normalize in place -> alpha
    for (int p = s0 + lane; p < s1; p += 32) {
#pragma unroll
        for (int h = 0; h < H; h++) g_ebuf[(size_t)p * H + h] *= inv[h];
    }
    __syncwarp();

    // phase 3: acc += alpha * feat[src]  (one warp-wide 512B gather per edge)
    float4 acc[NI];
#pragma unroll
    for (int i = 0; i < NI; i++) acc[i] = make_float4(0.f, 0.f, 0.f, 0.f);

    const float4* f4 = reinterpret_cast<const float4*>(feat);
    int p = s0;
    for (; p + 1 < s1; p += 2) {
        int sA = g_csrsrc[p];
        int sB = g_csrsrc[p + 1];
#pragma unroll
        for (int i = 0; i < NI; i++) {
            int c = lane + 32 * i;
            if ((C % 32 == 0) || (c < C)) {
                float aA = g_ebuf[(size_t)p * H + (c >> 3)];
                float aB = g_ebuf[(size_t)(p + 1) * H + (c >> 3)];
                float4 fA = f4[(size_t)sA * C + c];
                float4 fB = f4[(size_t)sB * C + c];
                acc[i].x += aA * fA.x + aB * fB.x;
                acc[i].y += aA * fA.y + aB * fB.y;
                acc[i].z += aA * fA.z + aB * fB.z;
                acc[i].w += aA * fA.w + aB * fB.w;
            }
        }
    }
    if (p < s1) {
        int s = g_csrsrc[p];
#pragma unroll
        for (int i = 0; i < NI; i++) {
            int c = lane + 32 * i;
            if ((C % 32 == 0) || (c < C)) {
                float a = g_ebuf[(size_t)p * H + (c >> 3)];
                float4 fv = f4[(size_t)s * C + c];
                acc[i].x += a * fv.x;
                acc[i].y += a * fv.y;
                acc[i].z += a * fv.z;
                acc[i].w += a * fv.w;
            }
        }
    }

    // epilogue: residual + bias + activation
    const float4* r4 = reinterpret_cast<const float4*>(res);
    const float4* b4 = reinterpret_cast<const float4*>(bias);
    float4* o4 = reinterpret_cast<float4*>(out);
#pragma unroll
    for (int i = 0; i < NI; i++) {
        int c = lane + 32 * i;
        if ((C % 32 == 0) || (c < C)) {
            float4 v = acc[i];
            if (RES) {
                float4 rv = r4[(size_t)n * C + c];
                v.x += rv.x; v.y += rv.y; v.z += rv.z; v.w += rv.w;
            }
            float4 bv = b4[c];
            v.x += bv.x; v.y += bv.y; v.z += bv.z; v.w += bv.w;
            if (ACT) {
                v.x = (v.x > 0.f) ? v.x : (__expf(v.x) - 1.f);
                v.y = (v.y > 0.f) ? v.y : (__expf(v.y) - 1.f);
                v.z = (v.z > 0.f) ? v.z : (__expf(v.z) - 1.f);
                v.w = (v.w > 0.f) ? v.w : (__expf(v.w) - 1.f);
            }
            o4[(size_t)n * C + c] = v;
        }
    }
}

// ---------------------------------------------------------------------------
// Final head mean: out[n,d] = mean_h rst3[n,h,d]
// ---------------------------------------------------------------------------
__global__ void mean_k(float* __restrict__ out) {
    int i = blockIdx.x * blockDim.x + threadIdx.x;
    if (i >= NN * 32) return;
    int n = i >> 5, d = i & 31;
    float s = 0.f;
#pragma unroll
    for (int h = 0; h < 6; h++) s += g_rst3[(size_t)n * 192 + h * 32 + d];
    out[i] = s * (1.f / 6.f);
}

// ---------------------------------------------------------------------------
// Launch
// ---------------------------------------------------------------------------
extern "C" void kernel_launch(void* const* d_in, const int* in_sizes, int n_in,
                              void* d_out, int out_size) {
    const float* x     = (const float*)d_in[0];
    const int*   src   = (const int*)d_in[1];
    const int*   dst   = (const int*)d_in[2];
    const float* W1    = (const float*)d_in[3];
    const float* al1   = (const float*)d_in[4];
    const float* ar1   = (const float*)d_in[5];
    const float* b1    = (const float*)d_in[6];
    const float* W2    = (const float*)d_in[7];
    const float* al2   = (const float*)d_in[8];
    const float* ar2   = (const float*)d_in[9];
    const float* b2    = (const float*)d_in[10];
    const float* W3    = (const float*)d_in[11];
    const float* al3   = (const float*)d_in[12];
    const float* ar3   = (const float*)d_in[13];
    const float* b3    = (const float*)d_in[14];
    const float* resW3 = (const float*)d_in[15];
    float* out = (float*)d_out;

    const int TB = 256;
    const int gridN  = (NN + TB - 1) / TB;
    const int gridE  = (EE + TB - 1) / TB;
    const int gridW  = (NN * 32 + TB - 1) / TB;   // warp-per-node kernels
    const int gridNH4 = (NN * 4 + TB - 1) / TB;
    const int gridNH6 = (NN * 6 + TB - 1) / TB;

    // device pointers to globals (fetch each call; cheap, graph-safe)
    float *p_h1, *p_h2, *p_feat, *p_res, *p_rst3;
    cudaGetSymbolAddress((void**)&p_h1,   g_h1);
    cudaGetSymbolAddress((void**)&p_h2,   g_h2);
    cudaGetSymbolAddress((void**)&p_feat, g_feat);
    cudaGetSymbolAddress((void**)&p_res,  g_res);
    cudaGetSymbolAddress((void**)&p_rst3, g_rst3);

    // CSR build (shared by all 3 layers)
    zero_cursor_k<<<gridN, TB>>>();
    count_k<<<gridE, TB>>>(dst);
    scan_k<<<1, 1024>>>();
    scatter_k<<<gridE, TB>>>(src, dst);

    // ----- layer 1: IN=128 -> (4,32), no residual, elu -----
    gemm_k<128><<<gridW, TB>>>(x, W1, p_feat);
    attn_k<4><<<gridNH4, TB>>>(p_feat, al1, ar1);
    gat_k<4, false, true><<<gridW, TB>>>(p_feat, nullptr, b1, p_h1);

    // ----- layer 2: 128 -> (4,32), identity residual, elu -----
    gemm_k<128><<<gridW, TB>>>(p_h1, W2, p_feat);
    attn_k<4><<<gridNH4, TB>>>(p_feat, al2, ar2);
    gat_k<4, true, true><<<gridW, TB>>>(p_feat, p_h1, b2, p_h2);

    // ----- layer 3: 128 -> (6,32), linear residual, no act -----
    gemm_k<192><<<gridW, TB>>>(p_h2, W3, p_feat);
    gemm_k<192><<<gridW, TB>>>(p_h2, resW3, p_res);
    attn_k<6><<<gridNH6, TB>>>(p_feat, al3, ar3);
    gat_k<6, true, false><<<gridW, TB>>>(p_feat, p_res, b3, p_rst3);

    // mean over heads
    mean_k<<<gridW, TB>>>(out);
}

// round 2
// speedup vs baseline: 1.7006x; 1.7006x over previous
#include <cuda_runtime.h>
#include <math.h>

#define NN 50000
#define EE 1600000

typedef unsigned long long ull;

// ---------------------------------------------------------------------------
// Scratch
// ---------------------------------------------------------------------------
__device__ float g_h1[NN * 128];
__device__ float g_h2[NN * 128];
__device__ float g_feat[NN * 192];
__device__ float g_res[NN * 192];
__device__ float g_el[NN * 6];
__device__ float g_er[NN * 6];
__device__ float g_ebuf[(size_t)EE * 6];
__device__ int   g_rowptr[NN + 1];
__device__ int   g_cursor[NN];
__device__ int   g_csrsrc[EE];

// ---------------------------------------------------------------------------
// f32x2 packed helpers (Blackwell)
// ---------------------------------------------------------------------------
__device__ __forceinline__ ull pack2(float x, float y) {
    ull r; asm("mov.b64 %0, {%1,%2};" : "=l"(r) : "f"(x), "f"(y)); return r;
}
__device__ __forceinline__ float2 unpack2(ull v) {
    float2 f; asm("mov.b64 {%0,%1}, %2;" : "=f"(f.x), "=f"(f.y) : "l"(v)); return f;
}
__device__ __forceinline__ void ffma2(ull& d, ull a, ull b) {
    asm("fma.rn.f32x2 %0, %1, %2, %0;" : "+l"(d) : "l"(a), "l"(b));
}

// ---------------------------------------------------------------------------
// CSR build
// ---------------------------------------------------------------------------
__global__ void zero_cursor_k() {
    int i = blockIdx.x * blockDim.x + threadIdx.x;
    if (i < NN) g_cursor[i] = 0;
}
__global__ void count_k(const int* __restrict__ dst) {
    int e = blockIdx.x * blockDim.x + threadIdx.x;
    if (e < EE) atomicAdd(&g_cursor[dst[e]], 1);
}
__global__ void scan_k() {
    const int NT = 1024;
    const int SEG = (NN + NT - 1) / NT;
    __shared__ int s[NT];
    int t = threadIdx.x;
    int lo = t * SEG, hi = lo + SEG; if (hi > NN) hi = NN;
    int sum = 0;
    for (int i = lo; i < hi; i++) sum += g_cursor[i];
    s[t] = sum;
    __syncthreads();
    for (int d = 1; d < NT; d <<= 1) {
        int v = (t >= d) ? s[t - d] : 0;
        __syncthreads();
        s[t] += v;
        __syncthreads();
    }
    int run = (t == 0) ? 0 : s[t - 1];
    for (int i = lo; i < hi; i++) {
        int c = g_cursor[i];
        g_rowptr[i] = run;
        g_cursor[i] = run;
        run += c;
    }
    if (t == NT - 1) g_rowptr[NN] = run;
}
__global__ void scatter_k(const int* __restrict__ src, const int* __restrict__ dst) {
    int e = blockIdx.x * blockDim.x + threadIdx.x;
    if (e < EE) {
        int p = atomicAdd(&g_cursor[dst[e]], 1);
        g_csrsrc[p] = src[e];
    }
}

// ---------------------------------------------------------------------------
// GEMM M=128: warp computes 8 nodes; W loads amortized 8x; FFMA2 packed
// ---------------------------------------------------------------------------
__global__ __launch_bounds__(256) void gemm128_k(const float* __restrict__ A,
                                                 const float* __restrict__ W,
                                                 float* __restrict__ C) {
    int w = (blockIdx.x * blockDim.x + threadIdx.x) >> 5;
    int n0 = w * 8;
    if (n0 >= NN) return;
    int lane = threadIdx.x & 31;

    const float4* A4 = reinterpret_cast<const float4*>(A);
    float4 a[8];
#pragma unroll
    for (int r = 0; r < 8; r++) a[r] = A4[(size_t)(n0 + r) * 32 + lane];

    ull acc[8][2];
#pragma unroll
    for (int r = 0; r < 8; r++) { acc[r][0] = 0ull; acc[r][1] = 0ull; }

    const float4* W4 = reinterpret_cast<const float4*>(W);
#pragma unroll 8
    for (int k = 0; k < 128; k++) {
        float4 wv = W4[(size_t)k * 32 + lane];
        ull wlo = pack2(wv.x, wv.y), whi = pack2(wv.z, wv.w);
        int sl = k >> 2;
#pragma unroll
        for (int r = 0; r < 8; r++) {
            float comp = ((k & 3) == 0) ? a[r].x : ((k & 3) == 1) ? a[r].y
                       : ((k & 3) == 2) ? a[r].z : a[r].w;
            float ak = __shfl_sync(0xffffffffu, comp, sl);
            ull aa = pack2(ak, ak);
            ffma2(acc[r][0], wlo, aa);
            ffma2(acc[r][1], whi, aa);
        }
    }

    float4* C4 = reinterpret_cast<float4*>(C);
#pragma unroll
    for (int r = 0; r < 8; r++) {
        float2 lo = unpack2(acc[r][0]), hi = unpack2(acc[r][1]);
        C4[(size_t)(n0 + r) * 32 + lane] = make_float4(lo.x, lo.y, hi.x, hi.y);
    }
}

// ---------------------------------------------------------------------------
// GEMM M=192: warp computes 4 nodes; exact float2 tiling (96 = 32 lanes x 3)
// ---------------------------------------------------------------------------
__global__ __launch_bounds__(256) void gemm192_k(const float* __restrict__ A,
                                                 const float* __restrict__ W,
                                                 float* __restrict__ C) {
    int w = (blockIdx.x * blockDim.x + threadIdx.x) >> 5;
    int n0 = w * 4;
    if (n0 >= NN) return;
    int lane = threadIdx.x & 31;

    const float4* A4 = reinterpret_cast<const float4*>(A);
    float4 a[4];
#pragma unroll
    for (int r = 0; r < 4; r++) a[r] = A4[(size_t)(n0 + r) * 32 + lane];

    ull acc[4][3];
#pragma unroll
    for (int r = 0; r < 4; r++) { acc[r][0] = acc[r][1] = acc[r][2] = 0ull; }

    const ull* W2 = reinterpret_cast<const ull*>(W);   // 96 float2 per row
#pragma unroll 8
    for (int k = 0; k < 128; k++) {
        ull w0 = W2[(size_t)k * 96 + lane];
        ull w1 = W2[(size_t)k * 96 + lane + 32];
        ull w2 = W2[(size_t)k * 96 + lane + 64];
        int sl = k >> 2;
#pragma unroll
        for (int r = 0; r < 4; r++) {
            float comp = ((k & 3) == 0) ? a[r].x : ((k & 3) == 1) ? a[r].y
                       : ((k & 3) == 2) ? a[r].z : a[r].w;
            float ak = __shfl_sync(0xffffffffu, comp, sl);
            ull aa = pack2(ak, ak);
            ffma2(acc[r][0], w0, aa);
            ffma2(acc[r][1], w1, aa);
            ffma2(acc[r][2], w2, aa);
        }
    }

    ull* C2 = reinterpret_cast<ull*>(C);
#pragma unroll
    for (int r = 0; r < 4; r++) {
#pragma unroll
        for (int j = 0; j < 3; j++)
            C2[(size_t)(n0 + r) * 96 + lane + 32 * j] = acc[r][j];
    }
}

// ---------------------------------------------------------------------------
// Attention projections
// ---------------------------------------------------------------------------
template <int H>
__global__ void attn_k(const float* __restrict__ feat,
                       const float* __restrict__ al,
                       const float* __restrict__ ar) {
    int i = blockIdx.x * blockDim.x + threadIdx.x;
    if (i >= NN * H) return;
    int n = i / H, h = i - n * H;
    const float4* f  = reinterpret_cast<const float4*>(feat) + (size_t)n * (H * 8) + h * 8;
    const float4* a4 = reinterpret_cast<const float4*>(al) + h * 8;
    const float4* r4 = reinterpret_cast<const float4*>(ar) + h * 8;
    float el = 0.f, er = 0.f;
#pragma unroll
    for (int j = 0; j < 8; j++) {
        float4 fv = f[j], av = a4[j], rv = r4[j];
        el += fv.x * av.x + fv.y * av.y + fv.z * av.z + fv.w * av.w;
        er += fv.x * rv.x + fv.y * rv.y + fv.z * rv.z + fv.w * rv.w;
    }
    g_el[i] = el;
    g_er[i] = er;
}

// ---------------------------------------------------------------------------
// Fused GAT aggregation, 2-pass (no max pass; exp clamped — values are tiny)
// ---------------------------------------------------------------------------
template <int H, bool RES, bool ACT, bool MEAN>
__global__ __launch_bounds__(256) void gat_k(const float* __restrict__ feat,
                                             const float* __restrict__ res,
                                             const float* __restrict__ bias,
                                             float* __restrict__ out) {
    constexpr int C  = H * 8;
    constexpr int NI = (C + 31) / 32;
    int n = (blockIdx.x * blockDim.x + threadIdx.x) >> 5;
    if (n >= NN) return;
    int lane = threadIdx.x & 31;

    int s0 = g_rowptr[n], s1 = g_rowptr[n + 1];

    float ern[H];
#pragma unroll
    for (int h = 0; h < H; h++) ern[h] = g_er[n * H + h];

    // ---- pass A: ex = exp(leakyrelu(el[src]+er[n])); store; sum ----
    float sm[H];
#pragma unroll
    for (int h = 0; h < H; h++) sm[h] = 0.f;

    const float2* el2 = reinterpret_cast<const float2*>(g_el);
    for (int p = s0 + lane; p < s1; p += 32) {
        int s = g_csrsrc[p];
        float ex[H];
#pragma unroll
        for (int j = 0; j < H / 2; j++) {
            float2 ev = el2[(size_t)s * (H / 2) + j];
            float e0 = ev.x + ern[2 * j];
            float e1 = ev.y + ern[2 * j + 1];
            e0 = (e0 > 0.f) ? e0 : 0.2f * e0;
            e1 = (e1 > 0.f) ? e1 : 0.2f * e1;
            ex[2 * j]     = __expf(fminf(e0, 60.f));
            ex[2 * j + 1] = __expf(fminf(e1, 60.f));
            sm[2 * j]     += ex[2 * j];
            sm[2 * j + 1] += ex[2 * j + 1];
        }
        if (H == 4) {
            reinterpret_cast<float4*>(g_ebuf)[p] =
                make_float4(ex[0], ex[1], ex[2], ex[3]);
        } else {
#pragma unroll
            for (int j = 0; j < H / 2; j++)
                reinterpret_cast<float2*>(g_ebuf)[(size_t)p * (H / 2) + j] =
                    make_float2(ex[2 * j], ex[2 * j + 1]);
        }
    }
#pragma unroll
    for (int h = 0; h < H; h++) {
#pragma unroll
        for (int o = 16; o > 0; o >>= 1)
            sm[h] += __shfl_xor_sync(0xffffffffu, sm[h], o);
    }
    float inv[H];
#pragma unroll
    for (int h = 0; h < H; h++) inv[h] = (sm[h] > 0.f) ? (1.f / sm[h]) : 0.f;

    // per-lane inv for each chunk (unrolled select, no local-mem indexing)
    float invc[NI];
#pragma unroll
    for (int i = 0; i < NI; i++) {
        int c = lane + 32 * i;
        int hh = c >> 3;
        float v = inv[0];
#pragma unroll
        for (int h = 1; h < H; h++) v = (hh == h) ? inv[h] : v;
        invc[i] = (c < C) ? v : 0.f;
    }

    // ---- pass B: acc += (ex * inv) * feat[src] ----
    float4 acc[NI];
#pragma unroll
    for (int i = 0; i < NI; i++) acc[i] = make_float4(0.f, 0.f, 0.f, 0.f);

    const float4* f4 = reinterpret_cast<const float4*>(feat);
    int p = s0;
    for (; p + 1 < s1; p += 2) {
        int sA = g_csrsrc[p];
        int sB = g_csrsrc[p + 1];
#pragma unroll
        for (int i = 0; i < NI; i++) {
            int c = lane + 32 * i;
            if ((C % 32 == 0) || (c < C)) {
                float aA = g_ebuf[(size_t)p * H + (c >> 3)] * invc[i];
                float aB = g_ebuf[(size_t)(p + 1) * H + (c >> 3)] * invc[i];
                float4 fA = f4[(size_t)sA * C + c];
                float4 fB = f4[(size_t)sB * C + c];
                acc[i].x += aA * fA.x + aB * fB.x;
                acc[i].y += aA * fA.y + aB * fB.y;
                acc[i].z += aA * fA.z + aB * fB.z;
                acc[i].w += aA * fA.w + aB * fB.w;
            }
        }
    }
    if (p < s1) {
        int s = g_csrsrc[p];
#pragma unroll
        for (int i = 0; i < NI; i++) {
            int c = lane + 32 * i;
            if ((C % 32 == 0) || (c < C)) {
                float a = g_ebuf[(size_t)p * H + (c >> 3)] * invc[i];
                float4 fv = f4[(size_t)s * C + c];
                acc[i].x += a * fv.x;
                acc[i].y += a * fv.y;
                acc[i].z += a * fv.z;
                acc[i].w += a * fv.w;
            }
        }
    }

    // ---- epilogue ----
    const float4* r4 = reinterpret_cast<const float4*>(res);
    const float4* b4 = reinterpret_cast<const float4*>(bias);
    float4 v[NI];
#pragma unroll
    for (int i = 0; i < NI; i++) {
        int c = lane + 32 * i;
        if ((C % 32 == 0) || (c < C)) {
            v[i] = acc[i];
            if (RES) {
                float4 rv = r4[(size_t)n * C + c];
                v[i].x += rv.x; v[i].y += rv.y; v[i].z += rv.z; v[i].w += rv.w;
            }
            float4 bv = b4[c];
            v[i].x += bv.x; v[i].y += bv.y; v[i].z += bv.z; v[i].w += bv.w;
            if (ACT) {
                v[i].x = (v[i].x > 0.f) ? v[i].x : (__expf(v[i].x) - 1.f);
                v[i].y = (v[i].y > 0.f) ? v[i].y : (__expf(v[i].y) - 1.f);
                v[i].z = (v[i].z > 0.f) ? v[i].z : (__expf(v[i].z) - 1.f);
                v[i].w = (v[i].w > 0.f) ? v[i].w : (__expf(v[i].w) - 1.f);
            }
        } else {
            v[i] = make_float4(0.f, 0.f, 0.f, 0.f);
        }
    }

    if (!MEAN) {
        float4* o4 = reinterpret_cast<float4*>(out);
#pragma unroll
        for (int i = 0; i < NI; i++) {
            int c = lane + 32 * i;
            if ((C % 32 == 0) || (c < C)) o4[(size_t)n * C + c] = v[i];
        }
    } else {
        // H == 6: mean over heads via xor-shuffles.
        // red0 at lane l(0..7) = sum of chunks {l, l+8, l+16, l+24} (heads 0-3)
        float4 r0 = v[0];
#pragma unroll
        for (int o = 8; o <= 16; o <<= 1) {
            r0.x += __shfl_xor_sync(0xffffffffu, r0.x, o);
            r0.y += __shfl_xor_sync(0xffffffffu, r0.y, o);
            r0.z += __shfl_xor_sync(0xffffffffu, r0.z, o);
            r0.w += __shfl_xor_sync(0xffffffffu, r0.w, o);
        }
        // red1 at lane l(0..15) = v[1](l) + v[1](l^8)  (heads 4-5)
        float4 r1 = v[1];
        r1.x += __shfl_xor_sync(0xffffffffu, r1.x, 8);
        r1.y += __shfl_xor_sync(0xffffffffu, r1.y, 8);
        r1.z += __shfl_xor_sync(0xffffffffu, r1.z, 8);
        r1.w += __shfl_xor_sync(0xffffffffu, r1.w, 8);
        if (lane < 8) {
            const float s6 = 1.f / 6.f;
            float4 o;
            o.x = (r0.x + r1.x) * s6;
            o.y = (r0.y + r1.y) * s6;
            o.z = (r0.z + r1.z) * s6;
            o.w = (r0.w + r1.w) * s6;
            reinterpret_cast<float4*>(out)[(size_t)n * 8 + lane] = o;
        }
    }
}

// ---------------------------------------------------------------------------
// Launch
// ---------------------------------------------------------------------------
extern "C" void kernel_launch(void* const* d_in, const int* in_sizes, int n_in,
                              void* d_out, int out_size) {
    const float* x     = (const float*)d_in[0];
    const int*   src   = (const int*)d_in[1];
    const int*   dst   = (const int*)d_in[2];
    const float* W1    = (const float*)d_in[3];
    const float* al1   = (const float*)d_in[4];
    const float* ar1   = (const float*)d_in[5];
    const float* b1    = (const float*)d_in[6];
    const float* W2    = (const float*)d_in[7];
    const float* al2   = (const float*)d_in[8];
    const float* ar2   = (const float*)d_in[9];
    const float* b2    = (const float*)d_in[10];
    const float* W3    = (const float*)d_in[11];
    const float* al3   = (const float*)d_in[12];
    const float* ar3   = (const float*)d_in[13];
    const float* b3    = (const float*)d_in[14];
    const float* resW3 = (const float*)d_in[15];
    float* out = (float*)d_out;

    const int TB = 256;
    const int gridN   = (NN + TB - 1) / TB;
    const int gridE   = (EE + TB - 1) / TB;
    const int gridW   = (NN * 32 + TB - 1) / TB;        // warp-per-node
    const int gridG8  = ((NN / 8) * 32 + TB - 1) / TB;  // gemm128 warps
    const int gridG4  = ((NN / 4) * 32 + TB - 1) / TB;  // gemm192 warps
    const int gridNH4 = (NN * 4 + TB - 1) / TB;
    const int gridNH6 = (NN * 6 + TB - 1) / TB;

    float *p_h1, *p_h2, *p_feat, *p_res;
    cudaGetSymbolAddress((void**)&p_h1,   g_h1);
    cudaGetSymbolAddress((void**)&p_h2,   g_h2);
    cudaGetSymbolAddress((void**)&p_feat, g_feat);
    cudaGetSymbolAddress((void**)&p_res,  g_res);

    // CSR build
    zero_cursor_k<<<gridN, TB>>>();
    count_k<<<gridE, TB>>>(dst);
    scan_k<<<1, 1024>>>();
    scatter_k<<<gridE, TB>>>(src, dst);

    // layer 1
    gemm128_k<<<gridG8, TB>>>(x, W1, p_feat);
    attn_k<4><<<gridNH4, TB>>>(p_feat, al1, ar1);
    gat_k<4, false, true, false><<<gridW, TB>>>(p_feat, nullptr, b1, p_h1);

    // layer 2
    gemm128_k<<<gridG8, TB>>>(p_h1, W2, p_feat);
    attn_k<4><<<gridNH4, TB>>>(p_feat, al2, ar2);
    gat_k<4, true, true, false><<<gridW, TB>>>(p_feat, p_h1, b2, p_h2);

    // layer 3 (mean fused)
    gemm192_k<<<gridG4, TB>>>(p_h2, W3, p_feat);
    gemm192_k<<<gridG4, TB>>>(p_h2, resW3, p_res);
    attn_k<6><<<gridNH6, TB>>>(p_feat, al3, ar3);
    gat_k<6, true, false, true><<<gridW, TB>>>(p_feat, p_res, b3, out);
}

// round 3
// speedup vs baseline: 1.9159x; 1.1266x over previous
#include <cuda_runtime.h>
#include <cuda_fp16.h>
#include <math.h>

#define NN 50000
#define EE 1600000

typedef unsigned long long ull;

// ---------------------------------------------------------------------------
// Scratch
// ---------------------------------------------------------------------------
__device__ float g_h1[NN * 128];
__device__ float g_h2[NN * 128];
__device__ uint2 g_feat_h[(size_t)NN * 48];   // fp16 feat: up to 192 halves/node
__device__ float g_res[NN * 192];
__device__ float g_el[NN * 6];
__device__ float g_er[NN * 6];
__device__ float g_ebuf[(size_t)EE * 6];
__device__ int   g_rowptr[NN + 1];
__device__ int   g_cursor[NN];
__device__ int   g_csrsrc[EE];

// ---------------------------------------------------------------------------
// f32x2 packed helpers
// ---------------------------------------------------------------------------
__device__ __forceinline__ ull pack2(float x, float y) {
    ull r; asm("mov.b64 %0, {%1,%2};" : "=l"(r) : "f"(x), "f"(y)); return r;
}
__device__ __forceinline__ float2 unpack2(ull v) {
    float2 f; asm("mov.b64 {%0,%1}, %2;" : "=f"(f.x), "=f"(f.y) : "l"(v)); return f;
}
__device__ __forceinline__ void ffma2(ull& d, ull a, ull b) {
    asm("fma.rn.f32x2 %0, %1, %2, %0;" : "+l"(d) : "l"(a), "l"(b));
}
__device__ __forceinline__ unsigned h2bits(__half2 h) {
    return *reinterpret_cast<unsigned*>(&h);
}

// ---------------------------------------------------------------------------
// CSR build
// ---------------------------------------------------------------------------
__global__ void zero_cursor_k() {
    int i = blockIdx.x * blockDim.x + threadIdx.x;
    if (i < NN) g_cursor[i] = 0;
}
__global__ void count_k(const int* __restrict__ dst) {
    int e = blockIdx.x * blockDim.x + threadIdx.x;
    if (e < EE) atomicAdd(&g_cursor[dst[e]], 1);
}
__global__ void scan_k() {
    const int NT = 1024;
    const int SEG = (NN + NT - 1) / NT;
    __shared__ int s[NT];
    int t = threadIdx.x;
    int lo = t * SEG, hi = lo + SEG; if (hi > NN) hi = NN;
    int sum = 0;
    for (int i = lo; i < hi; i++) sum += g_cursor[i];
    s[t] = sum;
    __syncthreads();
    for (int d = 1; d < NT; d <<= 1) {
        int v = (t >= d) ? s[t - d] : 0;
        __syncthreads();
        s[t] += v;
        __syncthreads();
    }
    int run = (t == 0) ? 0 : s[t - 1];
    for (int i = lo; i < hi; i++) {
        int c = g_cursor[i];
        g_rowptr[i] = run;
        g_cursor[i] = run;
        run += c;
    }
    if (t == NT - 1) g_rowptr[NN] = run;
}
__global__ void scatter_k(const int* __restrict__ src, const int* __restrict__ dst) {
    int e = blockIdx.x * blockDim.x + threadIdx.x;
    if (e < EE) {
        int p = atomicAdd(&g_cursor[dst[e]], 1);
        g_csrsrc[p] = src[e];
    }
}

// ---------------------------------------------------------------------------
// GEMM M=128 + fused attention projections; writes fp16 feat
// ---------------------------------------------------------------------------
__global__ __launch_bounds__(256) void gemm128_k(const float* __restrict__ A,
                                                 const float* __restrict__ W,
                                                 const float* __restrict__ al,
                                                 const float* __restrict__ ar) {
    int w = (blockIdx.x * blockDim.x + threadIdx.x) >> 5;
    int n0 = w * 8;
    if (n0 >= NN) return;
    int lane = threadIdx.x & 31;

    const float4* A4 = reinterpret_cast<const float4*>(A);
    float4 a[8];
#pragma unroll
    for (int r = 0; r < 8; r++) a[r] = A4[(size_t)(n0 + r) * 32 + lane];

    ull acc[8][2];
#pragma unroll
    for (int r = 0; r < 8; r++) { acc[r][0] = 0ull; acc[r][1] = 0ull; }

    const float4* W4 = reinterpret_cast<const float4*>(W);
#pragma unroll 8
    for (int k = 0; k < 128; k++) {
        float4 wv = W4[(size_t)k * 32 + lane];
        ull wlo = pack2(wv.x, wv.y), whi = pack2(wv.z, wv.w);
        int sl = k >> 2;
#pragma unroll
        for (int r = 0; r < 8; r++) {
            float comp = ((k & 3) == 0) ? a[r].x : ((k & 3) == 1) ? a[r].y
                       : ((k & 3) == 2) ? a[r].z : a[r].w;
            float ak = __shfl_sync(0xffffffffu, comp, sl);
            ull aa = pack2(ak, ak);
            ffma2(acc[r][0], wlo, aa);
            ffma2(acc[r][1], whi, aa);
        }
    }

    // lane holds cols 4*lane..4*lane+3 -> head = lane>>3 (8 lanes per head)
    float4 av = reinterpret_cast<const float4*>(al)[lane];
    float4 rv = reinterpret_cast<const float4*>(ar)[lane];
    int hh = lane >> 3;

#pragma unroll
    for (int r = 0; r < 8; r++) {
        float2 lo = unpack2(acc[r][0]), hi = unpack2(acc[r][1]);
        // attention partials + 8-lane segmented reduce
        float pl = lo.x * av.x + lo.y * av.y + hi.x * av.z + hi.y * av.w;
        float pr = lo.x * rv.x + lo.y * rv.y + hi.x * rv.z + hi.y * rv.w;
#pragma unroll
        for (int o = 1; o < 8; o <<= 1) {
            pl += __shfl_xor_sync(0xffffffffu, pl, o);
            pr += __shfl_xor_sync(0xffffffffu, pr, o);
        }
        if ((lane & 7) == 0) {
            g_el[(n0 + r) * 4 + hh] = pl;
            g_er[(n0 + r) * 4 + hh] = pr;
        }
        // fp16 feat store (4 halves = 8B per lane)
        uint2 u;
        u.x = h2bits(__float22half2_rn(lo));
        u.y = h2bits(__float22half2_rn(hi));
        g_feat_h[(size_t)(n0 + r) * 32 + lane] = u;
    }
}

// ---------------------------------------------------------------------------
// GEMM M=192: ATTN variant writes fp16 feat + el/er; RES variant writes fp32
// ---------------------------------------------------------------------------
template <bool ATTN>
__global__ __launch_bounds__(256) void gemm192_k(const float* __restrict__ A,
                                                 const float* __restrict__ W,
                                                 const float* __restrict__ al,
                                                 const float* __restrict__ ar,
                                                 float* __restrict__ Cres) {
    int w = (blockIdx.x * blockDim.x + threadIdx.x) >> 5;
    int n0 = w * 4;
    if (n0 >= NN) return;
    int lane = threadIdx.x & 31;

    const float4* A4 = reinterpret_cast<const float4*>(A);
    float4 a[4];
#pragma unroll
    for (int r = 0; r < 4; r++) a[r] = A4[(size_t)(n0 + r) * 32 + lane];

    ull acc[4][3];
#pragma unroll
    for (int r = 0; r < 4; r++) { acc[r][0] = acc[r][1] = acc[r][2] = 0ull; }

    const ull* W2 = reinterpret_cast<const ull*>(W);
#pragma unroll 8
    for (int k = 0; k < 128; k++) {
        ull w0 = W2[(size_t)k * 96 + lane];
        ull w1 = W2[(size_t)k * 96 + lane + 32];
        ull w2 = W2[(size_t)k * 96 + lane + 64];
        int sl = k >> 2;
#pragma unroll
        for (int r = 0; r < 4; r++) {
            float comp = ((k & 3) == 0) ? a[r].x : ((k & 3) == 1) ? a[r].y
                       : ((k & 3) == 2) ? a[r].z : a[r].w;
            float ak = __shfl_sync(0xffffffffu, comp, sl);
            ull aa = pack2(ak, ak);
            ffma2(acc[r][0], w0, aa);
            ffma2(acc[r][1], w1, aa);
            ffma2(acc[r][2], w2, aa);
        }
    }

    if (ATTN) {
        // half2-col c2 = lane + 32j (96 total); head = c2>>4 (16 lanes/head)
        const float2* al2 = reinterpret_cast<const float2*>(al);
        const float2* ar2 = reinterpret_cast<const float2*>(ar);
        float2 avj[3], rvj[3];
#pragma unroll
        for (int j = 0; j < 3; j++) { avj[j] = al2[lane + 32 * j]; rvj[j] = ar2[lane + 32 * j]; }
        unsigned* fh2 = reinterpret_cast<unsigned*>(g_feat_h);

#pragma unroll
        for (int r = 0; r < 4; r++) {
#pragma unroll
            for (int j = 0; j < 3; j++) {
                float2 f = unpack2(acc[r][j]);
                float pl = f.x * avj[j].x + f.y * avj[j].y;
                float pr = f.x * rvj[j].x + f.y * rvj[j].y;
#pragma unroll
                for (int o = 1; o < 16; o <<= 1) {
                    pl += __shfl_xor_sync(0xffffffffu, pl, o);
                    pr += __shfl_xor_sync(0xffffffffu, pr, o);
                }
                if ((lane & 15) == 0) {
                    int h = 2 * j + (lane >> 4);
                    g_el[(n0 + r) * 6 + h] = pl;
                    g_er[(n0 + r) * 6 + h] = pr;
                }
                fh2[(size_t)(n0 + r) * 96 + lane + 32 * j] =
                    h2bits(__float22half2_rn(f));
            }
        }
    } else {
        ull* C2 = reinterpret_cast<ull*>(Cres);
#pragma unroll
        for (int r = 0; r < 4; r++)
#pragma unroll
            for (int j = 0; j < 3; j++)
                C2[(size_t)(n0 + r) * 96 + lane + 32 * j] = acc[r][j];
    }
}

// ---------------------------------------------------------------------------
// Fused GAT aggregation (fp16 feat gather)
// ---------------------------------------------------------------------------
__device__ __forceinline__ void fma_h(float4& acc, float a, uint2 v) {
    __half2 hlo = *reinterpret_cast<__half2*>(&v.x);
    __half2 hhi = *reinterpret_cast<__half2*>(&v.y);
    float2 lo = __half22float2(hlo), hi = __half22float2(hhi);
    acc.x += a * lo.x; acc.y += a * lo.y;
    acc.z += a * hi.x; acc.w += a * hi.y;
}

template <int H, bool RES, bool ACT, bool MEAN>
__global__ __launch_bounds__(256) void gat_k(const float* __restrict__ res,
                                             const float* __restrict__ bias,
                                             float* __restrict__ out) {
    constexpr int C  = H * 8;            // 8B half4-chunks per node
    constexpr int NI = (C + 31) / 32;
    int n = (blockIdx.x * blockDim.x + threadIdx.x) >> 5;
    if (n >= NN) return;
    int lane = threadIdx.x & 31;

    int s0 = g_rowptr[n], s1 = g_rowptr[n + 1];

    float ern[H];
#pragma unroll
    for (int h = 0; h < H; h++) ern[h] = g_er[n * H + h];

    // ---- pass A: ex = exp(leakyrelu(el[src]+er[n])); store; sum ----
    float sm[H];
#pragma unroll
    for (int h = 0; h < H; h++) sm[h] = 0.f;

    const float2* el2 = reinterpret_cast<const float2*>(g_el);
    for (int p = s0 + lane; p < s1; p += 32) {
        int s = g_csrsrc[p];
        float ex[H];
#pragma unroll
        for (int j = 0; j < H / 2; j++) {
            float2 ev = el2[(size_t)s * (H / 2) + j];
            float e0 = ev.x + ern[2 * j];
            float e1 = ev.y + ern[2 * j + 1];
            e0 = (e0 > 0.f) ? e0 : 0.2f * e0;
            e1 = (e1 > 0.f) ? e1 : 0.2f * e1;
            ex[2 * j]     = __expf(fminf(e0, 60.f));
            ex[2 * j + 1] = __expf(fminf(e1, 60.f));
            sm[2 * j]     += ex[2 * j];
            sm[2 * j + 1] += ex[2 * j + 1];
        }
        if (H == 4) {
            reinterpret_cast<float4*>(g_ebuf)[p] =
                make_float4(ex[0], ex[1], ex[2], ex[3]);
        } else {
#pragma unroll
            for (int j = 0; j < H / 2; j++)
                reinterpret_cast<float2*>(g_ebuf)[(size_t)p * (H / 2) + j] =
                    make_float2(ex[2 * j], ex[2 * j + 1]);
        }
    }
#pragma unroll
    for (int h = 0; h < H; h++) {
#pragma unroll
        for (int o = 16; o > 0; o >>= 1)
            sm[h] += __shfl_xor_sync(0xffffffffu, sm[h], o);
    }
    float inv[H];
#pragma unroll
    for (int h = 0; h < H; h++) inv[h] = (sm[h] > 0.f) ? (1.f / sm[h]) : 0.f;

    float invc[NI];
#pragma unroll
    for (int i = 0; i < NI; i++) {
        int c = lane + 32 * i;
        int hh = c >> 3;
        float v = inv[0];
#pragma unroll
        for (int h = 1; h < H; h++) v = (hh == h) ? inv[h] : v;
        invc[i] = (c < C) ? v : 0.f;
    }

    // ---- pass B: acc += (ex*inv) * feat_h[src] ----
    float4 acc[NI];
#pragma unroll
    for (int i = 0; i < NI; i++) acc[i] = make_float4(0.f, 0.f, 0.f, 0.f);

    const uint2* fh = g_feat_h;
    int p = s0;
    if (H == 4) {
        int hh = lane >> 3;
        for (; p + 3 < s1; p += 4) {
            int sA = g_csrsrc[p],     sB = g_csrsrc[p + 1];
            int sC = g_csrsrc[p + 2], sD = g_csrsrc[p + 3];
            float aA = g_ebuf[(size_t)p * 4 + hh]       * invc[0];
            float aB = g_ebuf[(size_t)(p + 1) * 4 + hh] * invc[0];
            float aC = g_ebuf[(size_t)(p + 2) * 4 + hh] * invc[0];
            float aD = g_ebuf[(size_t)(p + 3) * 4 + hh] * invc[0];
            uint2 vA = fh[(size_t)sA * 32 + lane];
            uint2 vB = fh[(size_t)sB * 32 + lane];
            uint2 vC = fh[(size_t)sC * 32 + lane];
            uint2 vD = fh[(size_t)sD * 32 + lane];
            fma_h(acc[0], aA, vA);
            fma_h(acc[0], aB, vB);
            fma_h(acc[0], aC, vC);
            fma_h(acc[0], aD, vD);
        }
        for (; p < s1; p++) {
            int s = g_csrsrc[p];
            float a = g_ebuf[(size_t)p * 4 + hh] * invc[0];
            fma_h(acc[0], a, fh[(size_t)s * 32 + lane]);
        }
    } else {
        for (; p + 1 < s1; p += 2) {
            int sA = g_csrsrc[p];
            int sB = g_csrsrc[p + 1];
#pragma unroll
            for (int i = 0; i < NI; i++) {
                int c = lane + 32 * i;
                if (c < C) {
                    float aA = g_ebuf[(size_t)p * H + (c >> 3)] * invc[i];
                    float aB = g_ebuf[(size_t)(p + 1) * H + (c >> 3)] * invc[i];
                    uint2 vA = fh[(size_t)sA * C + c];
                    uint2 vB = fh[(size_t)sB * C + c];
                    fma_h(acc[i], aA, vA);
                    fma_h(acc[i], aB, vB);
                }
            }
        }
        if (p < s1) {
            int s = g_csrsrc[p];
#pragma unroll
            for (int i = 0; i < NI; i++) {
                int c = lane + 32 * i;
                if (c < C) {
                    float a = g_ebuf[(size_t)p * H + (c >> 3)] * invc[i];
                    fma_h(acc[i], a, fh[(size_t)s * C + c]);
                }
            }
        }
    }

    // ---- epilogue ----
    const float4* r4 = reinterpret_cast<const float4*>(res);
    const float4* b4 = reinterpret_cast<const float4*>(bias);
    float4 v[NI];
#pragma unroll
    for (int i = 0; i < NI; i++) {
        int c = lane + 32 * i;
        if ((C % 32 == 0) || (c < C)) {
            v[i] = acc[i];
            if (RES) {
                float4 rv = r4[(size_t)n * C + c];
                v[i].x += rv.x; v[i].y += rv.y; v[i].z += rv.z; v[i].w += rv.w;
            }
            float4 bv = b4[c];
            v[i].x += bv.x; v[i].y += bv.y; v[i].z += bv.z; v[i].w += bv.w;
            if (ACT) {
                v[i].x = (v[i].x > 0.f) ? v[i].x : (__expf(v[i].x) - 1.f);
                v[i].y = (v[i].y > 0.f) ? v[i].y : (__expf(v[i].y) - 1.f);
                v[i].z = (v[i].z > 0.f) ? v[i].z : (__expf(v[i].z) - 1.f);
                v[i].w = (v[i].w > 0.f) ? v[i].w : (__expf(v[i].w) - 1.f);
            }
        } else {
            v[i] = make_float4(0.f, 0.f, 0.f, 0.f);
        }
    }

    if (!MEAN) {
        float4* o4 = reinterpret_cast<float4*>(out);
#pragma unroll
        for (int i = 0; i < NI; i++) {
            int c = lane + 32 * i;
            if ((C % 32 == 0) || (c < C)) o4[(size_t)n * C + c] = v[i];
        }
    } else {
        float4 r0 = v[0];
#pragma unroll
        for (int o = 8; o <= 16; o <<= 1) {
            r0.x += __shfl_xor_sync(0xffffffffu, r0.x, o);
            r0.y += __shfl_xor_sync(0xffffffffu, r0.y, o);
            r0.z += __shfl_xor_sync(0xffffffffu, r0.z, o);
            r0.w += __shfl_xor_sync(0xffffffffu, r0.w, o);
        }
        float4 r1 = v[1];
        r1.x += __shfl_xor_sync(0xffffffffu, r1.x, 8);
        r1.y += __shfl_xor_sync(0xffffffffu, r1.y, 8);
        r1.z += __shfl_xor_sync(0xffffffffu, r1.z, 8);
        r1.w += __shfl_xor_sync(0xffffffffu, r1.w, 8);
        if (lane < 8) {
            const float s6 = 1.f / 6.f;
            float4 o;
            o.x = (r0.x + r1.x) * s6;
            o.y = (r0.y + r1.y) * s6;
            o.z = (r0.z + r1.z) * s6;
            o.w = (r0.w + r1.w) * s6;
            reinterpret_cast<float4*>(out)[(size_t)n * 8 + lane] = o;
        }
    }
}

// ---------------------------------------------------------------------------
// Launch
// ---------------------------------------------------------------------------
extern "C" void kernel_launch(void* const* d_in, const int* in_sizes, int n_in,
                              void* d_out, int out_size) {
    const float* x     = (const float*)d_in[0];
    const int*   src   = (const int*)d_in[1];
    const int*   dst   = (const int*)d_in[2];
    const float* W1    = (const float*)d_in[3];
    const float* al1   = (const float*)d_in[4];
    const float* ar1   = (const float*)d_in[5];
    const float* b1    = (const float*)d_in[6];
    const float* W2    = (const float*)d_in[7];
    const float* al2   = (const float*)d_in[8];
    const float* ar2   = (const float*)d_in[9];
    const float* b2    = (const float*)d_in[10];
    const float* W3    = (const float*)d_in[11];
    const float* al3   = (const float*)d_in[12];
    const float* ar3   = (const float*)d_in[13];
    const float* b3    = (const float*)d_in[14];
    const float* resW3 = (const float*)d_in[15];
    float* out = (float*)d_out;

    const int TB = 256;
    const int gridN  = (NN + TB - 1) / TB;
    const int gridE  = (EE + TB - 1) / TB;
    const int gridW  = (NN * 32 + TB - 1) / TB;
    const int gridG8 = ((NN / 8) * 32 + TB - 1) / TB;
    const int gridG4 = ((NN / 4) * 32 + TB - 1) / TB;

    float *p_h1, *p_h2, *p_res;
    cudaGetSymbolAddress((void**)&p_h1,  g_h1);
    cudaGetSymbolAddress((void**)&p_h2,  g_h2);
    cudaGetSymbolAddress((void**)&p_res, g_res);

    // CSR build
    zero_cursor_k<<<gridN, TB>>>();
    count_k<<<gridE, TB>>>(dst);
    scan_k<<<1, 1024>>>();
    scatter_k<<<gridE, TB>>>(src, dst);

    // layer 1
    gemm128_k<<<gridG8, TB>>>(x, W1, al1, ar1);
    gat_k<4, false, true, false><<<gridW, TB>>>(nullptr, b1, p_h1);

    // layer 2
    gemm128_k<<<gridG8, TB>>>(p_h1, W2, al2, ar2);
    gat_k<4, true, true, false><<<gridW, TB>>>(p_h1, b2, p_h2);

    // layer 3
    gemm192_k<true><<<gridG4, TB>>>(p_h2, W3, al3, ar3, nullptr);
    gemm192_k<false><<<gridG4, TB>>>(p_h2, resW3, nullptr, nullptr, p_res);
    gat_k<6, true, false, true><<<gridW, TB>>>(p_res, b3, out);
}

// round 4
// speedup vs baseline: 1.9612x; 1.0236x over previous
#include <cuda_runtime.h>
#include <cuda_fp16.h>
#include <math.h>

#define NN 50000
#define EE 1600000

typedef unsigned long long ull;

// ---------------------------------------------------------------------------
// Scratch
// ---------------------------------------------------------------------------
__device__ float g_h1[NN * 128];
__device__ float g_h2[NN * 128];
__device__ float g_res[NN * 192];
__device__ float g_er[NN * 6];
// packed per-node row: [el (H floats) | feat (H*32 halves)]
//   H=4: 16 + 256 = 272 B ; H=6: 24 + 384 = 408 B
__device__ __align__(16) char g_pack[(size_t)NN * 408];
__device__ int   g_rowptr[NN + 1];
__device__ int   g_cursor[NN];
__device__ int   g_csrsrc[EE];

// ---------------------------------------------------------------------------
// helpers
// ---------------------------------------------------------------------------
__device__ __forceinline__ ull pack2(float x, float y) {
    ull r; asm("mov.b64 %0, {%1,%2};" : "=l"(r) : "f"(x), "f"(y)); return r;
}
__device__ __forceinline__ float2 unpack2(ull v) {
    float2 f; asm("mov.b64 {%0,%1}, %2;" : "=f"(f.x), "=f"(f.y) : "l"(v)); return f;
}
__device__ __forceinline__ void ffma2(ull& d, ull a, ull b) {
    asm("fma.rn.f32x2 %0, %1, %2, %0;" : "+l"(d) : "l"(a), "l"(b));
}
__device__ __forceinline__ unsigned h2bits(__half2 h) {
    return *reinterpret_cast<unsigned*>(&h);
}
__device__ __forceinline__ void fma_h(float4& acc, float a, uint2 v) {
    __half2 hlo = *reinterpret_cast<__half2*>(&v.x);
    __half2 hhi = *reinterpret_cast<__half2*>(&v.y);
    float2 lo = __half22float2(hlo), hi = __half22float2(hhi);
    acc.x += a * lo.x; acc.y += a * lo.y;
    acc.z += a * hi.x; acc.w += a * hi.y;
}
__device__ __forceinline__ float edge_ex(float el, float ern) {
    float e = el + ern;
    e = (e > 0.f) ? e : 0.2f * e;
    return __expf(fminf(e, 60.f));
}

// ---------------------------------------------------------------------------
// CSR build
// ---------------------------------------------------------------------------
__global__ void zero_cursor_k() {
    int i = blockIdx.x * blockDim.x + threadIdx.x;
    if (i < NN) g_cursor[i] = 0;
}
__global__ void count_k(const int* __restrict__ dst) {
    int e = blockIdx.x * blockDim.x + threadIdx.x;
    if (e * 4 < EE) {
        int4 d = reinterpret_cast<const int4*>(dst)[e];
        atomicAdd(&g_cursor[d.x], 1);
        atomicAdd(&g_cursor[d.y], 1);
        atomicAdd(&g_cursor[d.z], 1);
        atomicAdd(&g_cursor[d.w], 1);
    }
}
__global__ void scan_k() {
    const int NT = 1024;
    const int SEG = (NN + NT - 1) / NT;
    __shared__ int s[NT];
    int t = threadIdx.x;
    int lo = t * SEG, hi = lo + SEG; if (hi > NN) hi = NN;
    int sum = 0;
    for (int i = lo; i < hi; i++) sum += g_cursor[i];
    s[t] = sum;
    __syncthreads();
    for (int d = 1; d < NT; d <<= 1) {
        int v = (t >= d) ? s[t - d] : 0;
        __syncthreads();
        s[t] += v;
        __syncthreads();
    }
    int run = (t == 0) ? 0 : s[t - 1];
    for (int i = lo; i < hi; i++) {
        int c = g_cursor[i];
        g_rowptr[i] = run;
        g_cursor[i] = run;
        run += c;
    }
    if (t == NT - 1) g_rowptr[NN] = run;
}
__global__ void scatter_k(const int* __restrict__ src, const int* __restrict__ dst) {
    int e = blockIdx.x * blockDim.x + threadIdx.x;
    if (e * 4 < EE) {
        int4 d = reinterpret_cast<const int4*>(dst)[e];
        int4 s = reinterpret_cast<const int4*>(src)[e];
        g_csrsrc[atomicAdd(&g_cursor[d.x], 1)] = s.x;
        g_csrsrc[atomicAdd(&g_cursor[d.y], 1)] = s.y;
        g_csrsrc[atomicAdd(&g_cursor[d.z], 1)] = s.z;
        g_csrsrc[atomicAdd(&g_cursor[d.w], 1)] = s.w;
    }
}

// ---------------------------------------------------------------------------
// GEMM M=128 + fused attention; writes packed row (el fp32 | feat fp16)
// ---------------------------------------------------------------------------
__global__ __launch_bounds__(256) void gemm128_k(const float* __restrict__ A,
                                                 const float* __restrict__ W,
                                                 const float* __restrict__ al,
                                                 const float* __restrict__ ar) {
    int w = (blockIdx.x * blockDim.x + threadIdx.x) >> 5;
    int n0 = w * 8;
    if (n0 >= NN) return;
    int lane = threadIdx.x & 31;

    const float4* A4 = reinterpret_cast<const float4*>(A);
    float4 a[8];
#pragma unroll
    for (int r = 0; r < 8; r++) a[r] = A4[(size_t)(n0 + r) * 32 + lane];

    ull acc[8][2];
#pragma unroll
    for (int r = 0; r < 8; r++) { acc[r][0] = 0ull; acc[r][1] = 0ull; }

    const float4* W4 = reinterpret_cast<const float4*>(W);
#pragma unroll 8
    for (int k = 0; k < 128; k++) {
        float4 wv = W4[(size_t)k * 32 + lane];
        ull wlo = pack2(wv.x, wv.y), whi = pack2(wv.z, wv.w);
        int sl = k >> 2;
#pragma unroll
        for (int r = 0; r < 8; r++) {
            float comp = ((k & 3) == 0) ? a[r].x : ((k & 3) == 1) ? a[r].y
                       : ((k & 3) == 2) ? a[r].z : a[r].w;
            float ak = __shfl_sync(0xffffffffu, comp, sl);
            ull aa = pack2(ak, ak);
            ffma2(acc[r][0], wlo, aa);
            ffma2(acc[r][1], whi, aa);
        }
    }

    float4 av = reinterpret_cast<const float4*>(al)[lane];
    float4 rv = reinterpret_cast<const float4*>(ar)[lane];
    int hh = lane >> 3;

#pragma unroll
    for (int r = 0; r < 8; r++) {
        char* row = g_pack + (size_t)(n0 + r) * 272;
        float2 lo = unpack2(acc[r][0]), hi = unpack2(acc[r][1]);
        float pl = lo.x * av.x + lo.y * av.y + hi.x * av.z + hi.y * av.w;
        float pr = lo.x * rv.x + lo.y * rv.y + hi.x * rv.z + hi.y * rv.w;
#pragma unroll
        for (int o = 1; o < 8; o <<= 1) {
            pl += __shfl_xor_sync(0xffffffffu, pl, o);
            pr += __shfl_xor_sync(0xffffffffu, pr, o);
        }
        if ((lane & 7) == 0) {
            reinterpret_cast<float*>(row)[hh] = pl;      // el packed
            g_er[(n0 + r) * 4 + hh] = pr;
        }
        uint2 u;
        u.x = h2bits(__float22half2_rn(lo));
        u.y = h2bits(__float22half2_rn(hi));
        *reinterpret_cast<uint2*>(row + 16 + 8 * lane) = u;
    }
}

// ---------------------------------------------------------------------------
// GEMM M=192: ATTN writes packed row + er; RES writes fp32 g_res
// ---------------------------------------------------------------------------
template <bool ATTN>
__global__ __launch_bounds__(256) void gemm192_k(const float* __restrict__ A,
                                                 const float* __restrict__ W,
                                                 const float* __restrict__ al,
                                                 const float* __restrict__ ar,
                                                 float* __restrict__ Cres) {
    int w = (blockIdx.x * blockDim.x + threadIdx.x) >> 5;
    int n0 = w * 4;
    if (n0 >= NN) return;
    int lane = threadIdx.x & 31;

    const float4* A4 = reinterpret_cast<const float4*>(A);
    float4 a[4];
#pragma unroll
    for (int r = 0; r < 4; r++) a[r] = A4[(size_t)(n0 + r) * 32 + lane];

    ull acc[4][3];
#pragma unroll
    for (int r = 0; r < 4; r++) { acc[r][0] = acc[r][1] = acc[r][2] = 0ull; }

    const ull* W2 = reinterpret_cast<const ull*>(W);
#pragma unroll 8
    for (int k = 0; k < 128; k++) {
        ull w0 = W2[(size_t)k * 96 + lane];
        ull w1 = W2[(size_t)k * 96 + lane + 32];
        ull w2 = W2[(size_t)k * 96 + lane + 64];
        int sl = k >> 2;
#pragma unroll
        for (int r = 0; r < 4; r++) {
            float comp = ((k & 3) == 0) ? a[r].x : ((k & 3) == 1) ? a[r].y
                       : ((k & 3) == 2) ? a[r].z : a[r].w;
            float ak = __shfl_sync(0xffffffffu, comp, sl);
            ull aa = pack2(ak, ak);
            ffma2(acc[r][0], w0, aa);
            ffma2(acc[r][1], w1, aa);
            ffma2(acc[r][2], w2, aa);
        }
    }

    if (ATTN) {
        const float2* al2 = reinterpret_cast<const float2*>(al);
        const float2* ar2 = reinterpret_cast<const float2*>(ar);
        float2 avj[3], rvj[3];
#pragma unroll
        for (int j = 0; j < 3; j++) { avj[j] = al2[lane + 32 * j]; rvj[j] = ar2[lane + 32 * j]; }

#pragma unroll
        for (int r = 0; r < 4; r++) {
            char* row = g_pack + (size_t)(n0 + r) * 408;
#pragma unroll
            for (int j = 0; j < 3; j++) {
                float2 f = unpack2(acc[r][j]);
                float pl = f.x * avj[j].x + f.y * avj[j].y;
                float pr = f.x * rvj[j].x + f.y * rvj[j].y;
#pragma unroll
                for (int o = 1; o < 16; o <<= 1) {
                    pl += __shfl_xor_sync(0xffffffffu, pl, o);
                    pr += __shfl_xor_sync(0xffffffffu, pr, o);
                }
                if ((lane & 15) == 0) {
                    int h = 2 * j + (lane >> 4);
                    reinterpret_cast<float*>(row)[h] = pl;   // el packed
                    g_er[(n0 + r) * 6 + h] = pr;
                }
                *reinterpret_cast<unsigned*>(row + 24 + 4 * (lane + 32 * j)) =
                    h2bits(__float22half2_rn(f));
            }
        }
    } else {
        ull* C2 = reinterpret_cast<ull*>(Cres);
#pragma unroll
        for (int r = 0; r < 4; r++)
#pragma unroll
            for (int j = 0; j < 3; j++)
                C2[(size_t)(n0 + r) * 96 + lane + 32 * j] = acc[r][j];
    }
}

// ---------------------------------------------------------------------------
// Single-pass GAT aggregation, H=4 (32 half-feats/node, stride 272)
// ---------------------------------------------------------------------------
template <bool RES, bool ACT>
__global__ __launch_bounds__(256) void gat4_k(const float* __restrict__ res,
                                              const float* __restrict__ bias,
                                              float* __restrict__ out) {
    int n = (blockIdx.x * blockDim.x + threadIdx.x) >> 5;
    if (n >= NN) return;
    int lane = threadIdx.x & 31;
    int hh = lane >> 3;

    int s0 = g_rowptr[n], s1 = g_rowptr[n + 1];
    float ern = g_er[n * 4 + hh];

    float sm = 0.f;
    float4 acc = make_float4(0.f, 0.f, 0.f, 0.f);
    int foff = 16 + 8 * lane;
    int eoff = 4 * hh;

    int p = s0;
    for (; p + 7 < s1; p += 8) {
        const char* r[8];
        float el[8];
        uint2 v[8];
#pragma unroll
        for (int q = 0; q < 8; q++) r[q] = g_pack + (size_t)g_csrsrc[p + q] * 272;
#pragma unroll
        for (int q = 0; q < 8; q++) el[q] = *reinterpret_cast<const float*>(r[q] + eoff);
#pragma unroll
        for (int q = 0; q < 8; q++) v[q] = *reinterpret_cast<const uint2*>(r[q] + foff);
#pragma unroll
        for (int q = 0; q < 8; q++) {
            float ex = edge_ex(el[q], ern);
            sm += ex;
            fma_h(acc, ex, v[q]);
        }
    }
    for (; p < s1; p++) {
        const char* r = g_pack + (size_t)g_csrsrc[p] * 272;
        float ex = edge_ex(*reinterpret_cast<const float*>(r + eoff), ern);
        sm += ex;
        fma_h(acc, ex, *reinterpret_cast<const uint2*>(r + foff));
    }

    float inv = (sm > 0.f) ? (1.f / sm) : 0.f;
    float4 v = make_float4(acc.x * inv, acc.y * inv, acc.z * inv, acc.w * inv);

    if (RES) {
        float4 rv = reinterpret_cast<const float4*>(res)[(size_t)n * 32 + lane];
        v.x += rv.x; v.y += rv.y; v.z += rv.z; v.w += rv.w;
    }
    float4 bv = reinterpret_cast<const float4*>(bias)[lane];
    v.x += bv.x; v.y += bv.y; v.z += bv.z; v.w += bv.w;
    if (ACT) {
        v.x = (v.x > 0.f) ? v.x : (__expf(v.x) - 1.f);
        v.y = (v.y > 0.f) ? v.y : (__expf(v.y) - 1.f);
        v.z = (v.z > 0.f) ? v.z : (__expf(v.z) - 1.f);
        v.w = (v.w > 0.f) ? v.w : (__expf(v.w) - 1.f);
    }
    reinterpret_cast<float4*>(out)[(size_t)n * 32 + lane] = v;
}

// ---------------------------------------------------------------------------
// Single-pass GAT aggregation, H=6 (48 half-feats/node, stride 408), linear
// residual, no act, fused head-mean
// ---------------------------------------------------------------------------
__global__ __launch_bounds__(256) void gat6_k(const float* __restrict__ res,
                                              const float* __restrict__ bias,
                                              float* __restrict__ out) {
    int n = (blockIdx.x * blockDim.x + threadIdx.x) >> 5;
    if (n >= NN) return;
    int lane = threadIdx.x & 31;
    bool hiL = (lane < 16);
    int hh0 = lane >> 3;            // heads 0..3
    int hh1 = 4 + (lane >> 3);      // heads 4..5 (valid for lane<16)

    int s0 = g_rowptr[n], s1 = g_rowptr[n + 1];
    float ern0 = g_er[n * 6 + hh0];
    float ern1 = hiL ? g_er[n * 6 + hh1] : 0.f;

    float sm0 = 0.f, sm1 = 0.f;
    float4 a0 = make_float4(0.f, 0.f, 0.f, 0.f);
    float4 a1 = make_float4(0.f, 0.f, 0.f, 0.f);
    int f0off = 24 + 8 * lane;
    int f1off = 24 + 8 * (lane + 32);
    int e0off = 4 * hh0, e1off = 4 * hh1;

    int p = s0;
    for (; p + 3 < s1; p += 4) {
        const char* r[4];
        float el0[4], el1[4];
        uint2 v0[4], v1[4];
#pragma unroll
        for (int q = 0; q < 4; q++) r[q] = g_pack + (size_t)g_csrsrc[p + q] * 408;
#pragma unroll
        for (int q = 0; q < 4; q++) {
            el0[q] = *reinterpret_cast<const float*>(r[q] + e0off);
            el1[q] = hiL ? *reinterpret_cast<const float*>(r[q] + e1off) : 0.f;
            v0[q] = *reinterpret_cast<const uint2*>(r[q] + f0off);
            v1[q] = hiL ? *reinterpret_cast<const uint2*>(r[q] + f1off)
                        : make_uint2(0u, 0u);
        }
#pragma unroll
        for (int q = 0; q < 4; q++) {
            float ex0 = edge_ex(el0[q], ern0);
            float ex1 = edge_ex(el1[q], ern1);
            sm0 += ex0; sm1 += ex1;
            fma_h(a0, ex0, v0[q]);
            fma_h(a1, ex1, v1[q]);
        }
    }
    for (; p < s1; p++) {
        const char* r = g_pack + (size_t)g_csrsrc[p] * 408;
        float ex0 = edge_ex(*reinterpret_cast<const float*>(r + e0off), ern0);
        float ex1 = edge_ex(hiL ? *reinterpret_cast<const float*>(r + e1off) : 0.f, ern1);
        sm0 += ex0; sm1 += ex1;
        fma_h(a0, ex0, *reinterpret_cast<const uint2*>(r + f0off));
        if (hiL) fma_h(a1, ex1, *reinterpret_cast<const uint2*>(r + f1off));
    }

    float inv0 = (sm0 > 0.f) ? (1.f / sm0) : 0.f;
    float inv1 = (sm1 > 0.f) ? (1.f / sm1) : 0.f;

    const float4* r4 = reinterpret_cast<const float4*>(res);
    const float4* b4 = reinterpret_cast<const float4*>(bias);

    float4 v0, v1;
    {
        float4 rv = r4[(size_t)n * 48 + lane];
        float4 bv = b4[lane];
        v0.x = a0.x * inv0 + rv.x + bv.x;
        v0.y = a0.y * inv0 + rv.y + bv.y;
        v0.z = a0.z * inv0 + rv.z + bv.z;
        v0.w = a0.w * inv0 + rv.w + bv.w;
    }
    if (hiL) {
        float4 rv = r4[(size_t)n * 48 + lane + 32];
        float4 bv = b4[lane + 32];
        v1.x = a1.x * inv1 + rv.x + bv.x;
        v1.y = a1.y * inv1 + rv.y + bv.y;
        v1.z = a1.z * inv1 + rv.z + bv.z;
        v1.w = a1.w * inv1 + rv.w + bv.w;
    } else {
        v1 = make_float4(0.f, 0.f, 0.f, 0.f);
    }

    // head mean: sum chunks {l, l+8, l+16, l+24} of v0 + {l, l+8} of v1
    float4 r0 = v0;
#pragma unroll
    for (int o = 8; o <= 16; o <<= 1) {
        r0.x += __shfl_xor_sync(0xffffffffu, r0.x, o);
        r0.y += __shfl_xor_sync(0xffffffffu, r0.y, o);
        r0.z += __shfl_xor_sync(0xffffffffu, r0.z, o);
        r0.w += __shfl_xor_sync(0xffffffffu, r0.w, o);
    }
    float4 r1 = v1;
    r1.x += __shfl_xor_sync(0xffffffffu, r1.x, 8);
    r1.y += __shfl_xor_sync(0xffffffffu, r1.y, 8);
    r1.z += __shfl_xor_sync(0xffffffffu, r1.z, 8);
    r1.w += __shfl_xor_sync(0xffffffffu, r1.w, 8);
    if (lane < 8) {
        const float s6 = 1.f / 6.f;
        float4 o;
        o.x = (r0.x + r1.x) * s6;
        o.y = (r0.y + r1.y) * s6;
        o.z = (r0.z + r1.z) * s6;
        o.w = (r0.w + r1.w) * s6;
        reinterpret_cast<float4*>(out)[(size_t)n * 8 + lane] = o;
    }
}

// ---------------------------------------------------------------------------
// Launch
// ---------------------------------------------------------------------------
extern "C" void kernel_launch(void* const* d_in, const int* in_sizes, int n_in,
                              void* d_out, int out_size) {
    const float* x     = (const float*)d_in[0];
    const int*   src   = (const int*)d_in[1];
    const int*   dst   = (const int*)d_in[2];
    const float* W1    = (const float*)d_in[3];
    const float* al1   = (const float*)d_in[4];
    const float* ar1   = (const float*)d_in[5];
    const float* b1    = (const float*)d_in[6];
    const float* W2    = (const float*)d_in[7];
    const float* al2   = (const float*)d_in[8];
    const float* ar2   = (const float*)d_in[9];
    const float* b2    = (const float*)d_in[10];
    const float* W3    = (const float*)d_in[11];
    const float* al3   = (const float*)d_in[12];
    const float* ar3   = (const float*)d_in[13];
    const float* b3    = (const float*)d_in[14];
    const float* resW3 = (const float*)d_in[15];
    float* out = (float*)d_out;

    const int TB = 256;
    const int gridN  = (NN + TB - 1) / TB;
    const int gridE4 = (EE / 4 + TB - 1) / TB;
    const int gridW  = (NN * 32 + TB - 1) / TB;
    const int gridG8 = ((NN / 8) * 32 + TB - 1) / TB;
    const int gridG4 = ((NN / 4) * 32 + TB - 1) / TB;

    float *p_h1, *p_h2, *p_res;
    cudaGetSymbolAddress((void**)&p_h1,  g_h1);
    cudaGetSymbolAddress((void**)&p_h2,  g_h2);
    cudaGetSymbolAddress((void**)&p_res, g_res);

    // CSR build
    zero_cursor_k<<<gridN, TB>>>();
    count_k<<<gridE4, TB>>>(dst);
    scan_k<<<1, 1024>>>();
    scatter_k<<<gridE4, TB>>>(src, dst);

    // layer 1
    gemm128_k<<<gridG8, TB>>>(x, W1, al1, ar1);
    gat4_k<false, true><<<gridW, TB>>>(nullptr, b1, p_h1);

    // layer 2
    gemm128_k<<<gridG8, TB>>>(p_h1, W2, al2, ar2);
    gat4_k<true, true><<<gridW, TB>>>(p_h1, b2, p_h2);

    // layer 3
    gemm192_k<true><<<gridG4, TB>>>(p_h2, W3, al3, ar3, nullptr);
    gemm192_k<false><<<gridG4, TB>>>(p_h2, resW3, nullptr, nullptr, p_res);
    gat6_k<<<gridW, TB>>>(p_res, b3, out);
}